// round 1
// baseline (speedup 1.0000x reference)
#include <cuda_runtime.h>
#include <math.h>

#define TOK   32768          // b*NY*NX tokens
#define DM    1024
#define NSEQ  1024           // b*NY sequences
#define SEQ   32             // NX
#define NH    16
#define HD    64

// ---------------- scratch (static device allocations) ----------------
static __device__ float g_X  [TOK * DM];        // router residual stream
static __device__ float g_H  [TOK * DM];        // LN out / attn out
static __device__ float g_QKV[TOK * 3 * DM];    // qkv, reused as masked xf
static __device__ float g_MLP[TOK * 4 * DM];    // mlp hidden
static __device__ float g_P1 [NSEQ * 16 * DM];  // pool factor-2 output
static __device__ float g_P2 [NSEQ * 8  * DM];  // pool factor-4 output
static __device__ int   g_CH [TOK];             // chosen (argmax)
static __device__ float g_MS [NSEQ];            // mask row-sums

// ---------------- helpers ----------------
__device__ __forceinline__ float gelu_tanh(float x) {
    const float c = 0.7978845608028654f;   // sqrt(2/pi)
    float x3 = x * x * x;
    return 0.5f * x * (1.0f + tanhf(c * (x + 0.044715f * x3)));
}

// ---------------- generic SGEMM: C = A(MxK) @ B(KxN) + bias [+epilogue] ----
// MODE 0: C = AB + bias
// MODE 1: C = gelu(AB + bias)
// MODE 2: C = res + AB + bias   (residual add; res may alias C)
template<int MODE>
__global__ __launch_bounds__(256) void sgemm_k(
    const float* __restrict__ A, const float* __restrict__ B,
    const float* __restrict__ bias, const float* __restrict__ res,
    float* __restrict__ C, int M, int N, int K)
{
    __shared__ float As[16][128];
    __shared__ float Bs[16][128];

    const int tid = threadIdx.x;
    const int m0 = blockIdx.y * 128;
    const int n0 = blockIdx.x * 128;

    const int tx = tid & 15;          // 0..15 -> col group
    const int ty = tid >> 4;          // 0..15 -> row group
    const int row0 = ty * 8;
    const int col0 = tx * 8;

    const int aRow = tid >> 2;        // 0..63
    const int aCol = (tid & 3) << 2;  // 0,4,8,12
    const int bRow = tid >> 5;        // 0..7
    const int bCol = (tid & 31) << 2; // 0..124

    float acc[8][8];
#pragma unroll
    for (int i = 0; i < 8; i++)
#pragma unroll
        for (int j = 0; j < 8; j++) acc[i][j] = 0.0f;

    const float* Ag = A + (size_t)m0 * K;

    for (int k0 = 0; k0 < K; k0 += 16) {
        float4 a0 = *(const float4*)(Ag + (size_t)aRow        * K + k0 + aCol);
        float4 a1 = *(const float4*)(Ag + (size_t)(aRow + 64) * K + k0 + aCol);
        As[aCol + 0][aRow] = a0.x; As[aCol + 1][aRow] = a0.y;
        As[aCol + 2][aRow] = a0.z; As[aCol + 3][aRow] = a0.w;
        As[aCol + 0][aRow + 64] = a1.x; As[aCol + 1][aRow + 64] = a1.y;
        As[aCol + 2][aRow + 64] = a1.z; As[aCol + 3][aRow + 64] = a1.w;

        float4 b0 = *(const float4*)(B + (size_t)(k0 + bRow)     * N + n0 + bCol);
        float4 b1 = *(const float4*)(B + (size_t)(k0 + bRow + 8) * N + n0 + bCol);
        *(float4*)&Bs[bRow][bCol]     = b0;
        *(float4*)&Bs[bRow + 8][bCol] = b1;

        __syncthreads();

#pragma unroll
        for (int kk = 0; kk < 16; kk++) {
            float a[8], b[8];
            *(float4*)(a)     = *(const float4*)&As[kk][row0];
            *(float4*)(a + 4) = *(const float4*)&As[kk][row0 + 4];
            *(float4*)(b)     = *(const float4*)&Bs[kk][col0];
            *(float4*)(b + 4) = *(const float4*)&Bs[kk][col0 + 4];
#pragma unroll
            for (int i = 0; i < 8; i++)
#pragma unroll
                for (int j = 0; j < 8; j++)
                    acc[i][j] += a[i] * b[j];
        }
        __syncthreads();
    }

    float bv[8];
#pragma unroll
    for (int j = 0; j < 8; j++) bv[j] = bias[n0 + col0 + j];

#pragma unroll
    for (int i = 0; i < 8; i++) {
        size_t off = (size_t)(m0 + row0 + i) * N + n0 + col0;
        float v[8];
#pragma unroll
        for (int j = 0; j < 8; j++) {
            float t = acc[i][j] + bv[j];
            if (MODE == 1) t = gelu_tanh(t);
            if (MODE == 2) t += res[off + j];
            v[j] = t;
        }
        *(float4*)(C + off)     = make_float4(v[0], v[1], v[2], v[3]);
        *(float4*)(C + off + 4) = make_float4(v[4], v[5], v[6], v[7]);
    }
}

// ---------------- LayerNorm (one block of 256 per token row) ----------------
__global__ __launch_bounds__(256) void ln_k(
    const float* __restrict__ X, const float* __restrict__ w,
    const float* __restrict__ b, float* __restrict__ out)
{
    const int row = blockIdx.x, tid = threadIdx.x;
    const int lane = tid & 31, wid = tid >> 5;
    __shared__ float red[8];

    float4 xv = ((const float4*)(X + (size_t)row * DM))[tid];
    float s = xv.x + xv.y + xv.z + xv.w;
#pragma unroll
    for (int o = 16; o > 0; o >>= 1) s += __shfl_xor_sync(0xffffffffu, s, o);
    if (lane == 0) red[wid] = s;
    __syncthreads();
    s = red[0] + red[1] + red[2] + red[3] + red[4] + red[5] + red[6] + red[7];
    float mean = s * (1.0f / 1024.0f);

    float dx = xv.x - mean, dy = xv.y - mean, dz = xv.z - mean, dw = xv.w - mean;
    float sq = dx * dx + dy * dy + dz * dz + dw * dw;
#pragma unroll
    for (int o = 16; o > 0; o >>= 1) sq += __shfl_xor_sync(0xffffffffu, sq, o);
    __syncthreads();
    if (lane == 0) red[wid] = sq;
    __syncthreads();
    sq = red[0] + red[1] + red[2] + red[3] + red[4] + red[5] + red[6] + red[7];
    float rstd = rsqrtf(sq * (1.0f / 1024.0f) + 1e-5f);

    float4 wv = ((const float4*)w)[tid];
    float4 bvv = ((const float4*)b)[tid];
    float4 o4;
    o4.x = dx * rstd * wv.x + bvv.x;
    o4.y = dy * rstd * wv.y + bvv.y;
    o4.z = dz * rstd * wv.z + bvv.z;
    o4.w = dw * rstd * wv.w + bvv.w;
    ((float4*)(out + (size_t)row * DM))[tid] = o4;
}

// ---------------- attention (one block per (seq, head)) ----------------
__global__ __launch_bounds__(256) void attn_k(
    const float* __restrict__ QKV, const float* __restrict__ mask,
    float* __restrict__ O)
{
    __shared__ float qs[SEQ * HD];
    __shared__ float ks[SEQ * (HD + 1)];
    __shared__ float vs[SEQ * (HD + 1)];
    __shared__ float sc[SEQ * SEQ];

    const int bseq = blockIdx.x >> 4;
    const int h    = blockIdx.x & 15;
    const int tid  = threadIdx.x;

    const float* base = QKV + (size_t)(bseq * SEQ) * 3072 + h * HD;
    for (int i = tid; i < SEQ * HD; i += 256) {
        int t = i >> 6, d = i & 63;
        qs[t * HD + d]       = base[(size_t)t * 3072 + d];
        ks[t * (HD + 1) + d] = base[(size_t)t * 3072 + 1024 + d];
        vs[t * (HD + 1) + d] = base[(size_t)t * 3072 + 2048 + d];
    }
    __syncthreads();

    for (int i = tid; i < SEQ * SEQ; i += 256) {
        int qi = i >> 5, ki = i & 31;
        float s = 0.0f;
#pragma unroll
        for (int d = 0; d < HD; d++) s += qs[qi * HD + d] * ks[ki * (HD + 1) + d];
        float mb = (mask[bseq * SEQ + ki] > 0.0f) ? 0.0f : -1e9f;
        sc[i] = s * 0.125f + mb;   // 1/sqrt(64)
    }
    __syncthreads();

    {   // softmax: each warp handles 4 rows, lane = key index
        int wid = tid >> 5, lane = tid & 31;
        for (int r = wid; r < SEQ; r += 8) {
            float v = sc[r * SEQ + lane];
            float mx = v;
#pragma unroll
            for (int o = 16; o > 0; o >>= 1) mx = fmaxf(mx, __shfl_xor_sync(0xffffffffu, mx, o));
            float e = expf(v - mx);
            float su = e;
#pragma unroll
            for (int o = 16; o > 0; o >>= 1) su += __shfl_xor_sync(0xffffffffu, su, o);
            sc[r * SEQ + lane] = e / su;
        }
    }
    __syncthreads();

    for (int i = tid; i < SEQ * HD; i += 256) {
        int t = i >> 6, d = i & 63;
        float o = 0.0f;
#pragma unroll
        for (int k = 0; k < SEQ; k++) o += sc[t * SEQ + k] * vs[k * (HD + 1) + d];
        O[(size_t)(bseq * SEQ + t) * DM + h * HD + d] = o;
    }
}

// ---------------- logits + argmax (one warp per token) ----------------
__global__ void logits_k(const float* __restrict__ X, const float* __restrict__ W,
                         const float* __restrict__ bias, int* __restrict__ chosen)
{
    int gtid = blockIdx.x * blockDim.x + threadIdx.x;
    int row  = gtid >> 5;
    int lane = threadIdx.x & 31;
    if (row >= TOK) return;
    const float* xr = X + (size_t)row * DM;
    float a0 = 0, a1 = 0, a2 = 0;
    for (int j = lane; j < DM; j += 32) {
        float x = xr[j];
        a0 += x * W[j * 3 + 0];
        a1 += x * W[j * 3 + 1];
        a2 += x * W[j * 3 + 2];
    }
#pragma unroll
    for (int o = 16; o > 0; o >>= 1) {
        a0 += __shfl_xor_sync(0xffffffffu, a0, o);
        a1 += __shfl_xor_sync(0xffffffffu, a1, o);
        a2 += __shfl_xor_sync(0xffffffffu, a2, o);
    }
    if (lane == 0) {
        a0 += bias[0]; a1 += bias[1]; a2 += bias[2];
        int idx = 0; float best = a0;
        if (a1 > best) { best = a1; idx = 1; }
        if (a2 > best) { best = a2; idx = 2; }
        chosen[row] = idx;
    }
}

// ---------------- small utility kernels ----------------
__global__ void copy_k(const float4* __restrict__ src, float4* __restrict__ dst, int n4) {
    int i = blockIdx.x * 256 + threadIdx.x;
    if (i < n4) dst[i] = src[i];
}

__global__ void maskmul_k(const float4* __restrict__ x, const float* __restrict__ mask,
                          float4* __restrict__ out, int n4) {
    int i = blockIdx.x * 256 + threadIdx.x;
    if (i < n4) {
        float m = mask[i >> 8];   // 256 float4 per 1024-float token row
        float4 v = x[i];
        v.x *= m; v.y *= m; v.z *= m; v.w *= m;
        out[i] = v;
    }
}

__global__ void msum_k(const float* __restrict__ mask, float* __restrict__ ms) {
    int b = blockIdx.x, lane = threadIdx.x;
    float m = mask[b * SEQ + lane];
#pragma unroll
    for (int o = 16; o > 0; o >>= 1) m += __shfl_xor_sync(0xffffffffu, m, o);
    if (lane == 0) ms[b] = m;
}

__global__ void compress_k(const int* __restrict__ chosen, const float* __restrict__ mask,
                           float* __restrict__ comp) {
    int b = blockIdx.x, lane = threadIdx.x;
    float c = (float)chosen[b * SEQ + lane] / 3.0f;
    float m = mask[b * SEQ + lane];
    float num = c * m, den = m;
#pragma unroll
    for (int o = 16; o > 0; o >>= 1) {
        num += __shfl_xor_sync(0xffffffffu, num, o);
        den += __shfl_xor_sync(0xffffffffu, den, o);
    }
    if (lane == 0) comp[b] = num / den;
}

// ---------------- final assembly: outputs + masks ----------------
__global__ __launch_bounds__(256) void assemble_k(
    const float* __restrict__ x, const float* __restrict__ mask,
    const int* __restrict__ chosen, const float* __restrict__ msum,
    const float* __restrict__ P1, const float* __restrict__ P2,
    const float* __restrict__ emb,
    float* __restrict__ out, float* __restrict__ masks_out)
{
    const int r = blockIdx.x;
    const int b = r >> 5, pos = r & 31;
    const int tid = threadIdx.x;
    const int c = chosen[r];
    const float ms = msum[b];

    float4* o4 = (float4*)(out + (size_t)r * DM);
    float maskv;

    if (c == 0) {
        o4[tid] = ((const float4*)(x + (size_t)r * DM))[tid];
        maskv = mask[r];
    } else if (c == 1) {
        float nm = ((float)pos < ms * 0.5f) ? 1.0f : 0.0f;
        float4 e = ((const float4*)emb)[tid];
        float4 pv = make_float4(0, 0, 0, 0);
        if (pos < 16) pv = ((const float4*)(P1 + (size_t)(b * 16 + pos) * DM))[tid];
        o4[tid] = make_float4(pv.x * nm + e.x, pv.y * nm + e.y,
                              pv.z * nm + e.z, pv.w * nm + e.w);
        maskv = nm;
    } else {
        float nm = ((float)pos < ms * 0.25f) ? 1.0f : 0.0f;
        float4 e = ((const float4*)(emb + DM))[tid];
        float4 pv = make_float4(0, 0, 0, 0);
        if (pos < 8) pv = ((const float4*)(P2 + (size_t)(b * 8 + pos) * DM))[tid];
        o4[tid] = make_float4(pv.x * nm + e.x, pv.y * nm + e.y,
                              pv.z * nm + e.z, pv.w * nm + e.w);
        maskv = nm;
    }
    if (tid == 0) masks_out[r] = maskv;
}

// ---------------- launch ----------------
extern "C" void kernel_launch(void* const* d_in, const int* in_sizes, int n_in,
                              void* d_out, int out_size)
{
    const float* x     = (const float*)d_in[0];
    const float* mask  = (const float*)d_in[1];
    const float* ln1_w = (const float*)d_in[2];
    const float* ln1_b = (const float*)d_in[3];
    const float* wqkv  = (const float*)d_in[4];
    const float* bqkv  = (const float*)d_in[5];
    const float* wo    = (const float*)d_in[6];
    const float* bo    = (const float*)d_in[7];
    const float* ln2_w = (const float*)d_in[8];
    const float* ln2_b = (const float*)d_in[9];
    const float* w1    = (const float*)d_in[10];
    const float* b1    = (const float*)d_in[11];
    const float* w2    = (const float*)d_in[12];
    const float* b2    = (const float*)d_in[13];
    const float* rfw   = (const float*)d_in[14];
    const float* rfb   = (const float*)d_in[15];
    const float* p2w   = (const float*)d_in[16];
    const float* p2b   = (const float*)d_in[17];
    const float* p4w   = (const float*)d_in[18];
    const float* p4b   = (const float*)d_in[19];
    const float* femb  = (const float*)d_in[20];

    float *X, *H, *QKV, *MLP, *P1, *P2, *MS;
    int* CH;
    cudaGetSymbolAddress((void**)&X,   g_X);
    cudaGetSymbolAddress((void**)&H,   g_H);
    cudaGetSymbolAddress((void**)&QKV, g_QKV);
    cudaGetSymbolAddress((void**)&MLP, g_MLP);
    cudaGetSymbolAddress((void**)&P1,  g_P1);
    cudaGetSymbolAddress((void**)&P2,  g_P2);
    cudaGetSymbolAddress((void**)&MS,  g_MS);
    cudaGetSymbolAddress((void**)&CH,  g_CH);

    const int n4 = TOK * DM / 4;             // 8388608 float4
    copy_k<<<n4 / 256, 256>>>((const float4*)x, (float4*)X, n4);

    for (int i = 0; i < 2; i++) {
        ln_k<<<TOK, 256>>>(X, ln1_w + i * DM, ln1_b + i * DM, H);
        sgemm_k<0><<<dim3(3072 / 128, TOK / 128), 256>>>(
            H, wqkv + (size_t)i * DM * 3072, bqkv + i * 3072, nullptr, QKV, TOK, 3072, DM);
        attn_k<<<NSEQ * NH, 256>>>(QKV, mask, H);
        sgemm_k<2><<<dim3(DM / 128, TOK / 128), 256>>>(
            H, wo + (size_t)i * DM * DM, bo + i * DM, X, X, TOK, DM, DM);
        ln_k<<<TOK, 256>>>(X, ln2_w + i * DM, ln2_b + i * DM, H);
        sgemm_k<1><<<dim3(4096 / 128, TOK / 128), 256>>>(
            H, w1 + (size_t)i * DM * 4096, b1 + i * 4096, nullptr, MLP, TOK, 4096, DM);
        sgemm_k<2><<<dim3(DM / 128, TOK / 128), 256>>>(
            MLP, w2 + (size_t)i * 4096 * DM, b2 + i * DM, X, X, TOK, DM, 4096);
    }

    logits_k<<<TOK / 8, 256>>>(X, rfw, rfb, CH);

    maskmul_k<<<n4 / 256, 256>>>((const float4*)x, mask, (float4*)QKV, n4);
    sgemm_k<0><<<dim3(DM / 128, 16384 / 128), 256>>>(QKV, p2w, p2b, nullptr, P1, 16384, DM, 2048);
    sgemm_k<0><<<dim3(DM / 128, 8192 / 128), 256>>>(QKV, p4w, p4b, nullptr, P2, 8192, DM, 4096);

    msum_k<<<NSEQ, 32>>>(mask, MS);

    float* out = (float*)d_out;
    assemble_k<<<TOK, 256>>>(x, mask, CH, MS, P1, P2, femb, out, out + (size_t)TOK * DM);
    compress_k<<<NSEQ, 32>>>(CH, mask, out + (size_t)TOK * DM + TOK);
}